// round 1
// baseline (speedup 1.0000x reference)
#include <cuda_runtime.h>

// ---------------- problem constants ----------------
static constexpr int NCOLS = 99;
static constexpr int TILE_R = 96;       // rows per tile (38016 B smem, < 48K static)
static constexpr int TPB_MAIN = 96;     // one thread per row in phase 2

// ---------------- global accumulators (device scratch; no allocation) ------
__device__ float g_mse, g_dot, g_lse;
__device__ unsigned g_minkey[10], g_maxkey[10];
__device__ unsigned g_hist[200];        // [sex(2)][feat(10)][bin(10)]

// monotonic float<->uint key (order-preserving incl. negatives)
__device__ __forceinline__ unsigned f2key(float f) {
    unsigned u = __float_as_uint(f);
    return (u & 0x80000000u) ? ~u : (u | 0x80000000u);
}
__device__ __forceinline__ float key2f(unsigned k) {
    unsigned u = (k & 0x80000000u) ? (k ^ 0x80000000u) : ~k;
    return __uint_as_float(u);
}

// ---------------- init ----------------
__global__ void k_init() {
    int t = threadIdx.x;
    if (t == 0) { g_mse = 0.f; g_dot = 0.f; g_lse = 0.f; }
    if (t < 10) { g_minkey[t] = 0xFFFFFFFFu; g_maxkey[t] = 0u; }
    if (t < 200) g_hist[t] = 0u;
}

// ---------------- per-column min/max of encoded[:, 0:10] ----------------
__global__ void k_minmax(const float4* __restrict__ e4, int B) {
    float mn[10], mx[10];
    const float INF = __int_as_float(0x7f800000);
#pragma unroll
    for (int i = 0; i < 10; i++) { mn[i] = INF; mx[i] = -INF; }
    int stride = gridDim.x * blockDim.x;
    for (int r = blockIdx.x * blockDim.x + threadIdx.x; r < B; r += stride) {
        float4 a = e4[3 * r], b = e4[3 * r + 1], c = e4[3 * r + 2];
        float v[10] = {a.x, a.y, a.z, a.w, b.x, b.y, b.z, b.w, c.x, c.y};
#pragma unroll
        for (int i = 0; i < 10; i++) {
            mn[i] = fminf(mn[i], v[i]);
            mx[i] = fmaxf(mx[i], v[i]);
        }
    }
#pragma unroll
    for (int i = 0; i < 10; i++) {
#pragma unroll
        for (int o = 16; o > 0; o >>= 1) {
            mn[i] = fminf(mn[i], __shfl_xor_sync(0xFFFFFFFFu, mn[i], o));
            mx[i] = fmaxf(mx[i], __shfl_xor_sync(0xFFFFFFFFu, mx[i], o));
        }
    }
    if ((threadIdx.x & 31) == 0) {
#pragma unroll
        for (int i = 0; i < 10; i++) {
            atomicMin(&g_minkey[i], f2key(mn[i]));
            atomicMax(&g_maxkey[i], f2key(mx[i]));
        }
    }
}

// ---------------- histogram (needs min/max done) ----------------
__global__ void k_hist(const float4* __restrict__ e4, int B) {
    __shared__ unsigned sh[200];
    __shared__ float smn[10], swid[10];
    int t = threadIdx.x;
    if (t < 200) sh[t] = 0u;
    if (t < 10) {
        float mn = key2f(g_minkey[t]);
        float mx = key2f(g_maxkey[t]);
        smn[t] = mn;
        swid[t] = fmaxf(mx - mn, 1e-12f);
    }
    __syncthreads();
    int stride = gridDim.x * blockDim.x;
    for (int r = blockIdx.x * blockDim.x + t; r < B; r += stride) {
        float4 a = e4[3 * r], b = e4[3 * r + 1], c = e4[3 * r + 2];
        int base = (c.w == 0.0f) ? 0 : 100;   // col 11 = sex; 0 -> m, 1 -> f
        float v[10] = {a.x, a.y, a.z, a.w, b.x, b.y, b.z, b.w, c.x, c.y};
#pragma unroll
        for (int i = 0; i < 10; i++) {
            float tt = (v[i] - smn[i]) / swid[i] * 10.0f;  // match jnp op order
            int bi = (int)floorf(tt);
            bi = min(9, max(0, bi));
            atomicAdd(&sh[base + i * 10 + bi], 1u);
        }
    }
    __syncthreads();
    if (t < 200) atomicAdd(&g_hist[t], sh[t]);
}

// ---------------- main: MSE + CE (dot elementwise, LSE via smem tiles) -----
template <int S, int E>
__device__ __forceinline__ float lse_blk(const float* row) {
    float s = 0.f;
#pragma unroll
    for (int c = S; c < E; ++c) s += __expf(row[c]);
    return __logf(s);
}

__device__ __forceinline__ void classify_acc(float d, float t, int c,
                                             float& a_mse, float& a_dot) {
    bool m = (c == 0) | (c == 55) | (c == 56) | (c == 57);
    float df = d - t;
    if (m) a_mse = fmaf(df, df, a_mse);
    else   a_dot = fmaf(d, t, a_dot);
}

__global__ void __launch_bounds__(TPB_MAIN)
k_main(const float* __restrict__ dec, const float* __restrict__ tru, int B) {
    __shared__ float sm[TILE_R * NCOLS];   // 38016 B
    __shared__ float wred[3][4];           // 3 warps
    int nt = (B + TILE_R - 1) / TILE_R;
    float a_mse = 0.f, a_dot = 0.f, a_lse = 0.f;

    for (int tile = blockIdx.x; tile < nt; tile += gridDim.x) {
        int r0 = tile * TILE_R;
        int rows = min(TILE_R, B - r0);
        size_t ebase = (size_t)r0 * NCOLS;

        if (rows == TILE_R) {
            const float4* d4 = (const float4*)(dec + ebase);
            const float4* t4 = (const float4*)(tru + ebase);
            float4* s4 = (float4*)sm;
            int c0 = (threadIdx.x * 4) % 99;
#pragma unroll 2
            for (int i = threadIdx.x; i < TILE_R * NCOLS / 4; i += TPB_MAIN) {
                float4 d = d4[i], t = t4[i];
                s4[i] = d;
                float dv[4] = {d.x, d.y, d.z, d.w};
                float tv[4] = {t.x, t.y, t.z, t.w};
                int c = c0;
#pragma unroll
                for (int j = 0; j < 4; j++) {
                    classify_acc(dv[j], tv[j], c, a_mse, a_dot);
                    c++; if (c == 99) c = 0;
                }
                c0 += 87;                  // (96*4) % 99
                if (c0 >= 99) c0 -= 99;
            }
        } else {
            int ne = rows * NCOLS;
            for (int e = threadIdx.x; e < ne; e += TPB_MAIN) {
                float d = dec[ebase + e], t = tru[ebase + e];
                sm[e] = d;
                classify_acc(d, t, e % 99, a_mse, a_dot);
            }
        }
        __syncthreads();

        if (threadIdx.x < rows) {
            const float* row = sm + threadIdx.x * NCOLS;
            a_lse += lse_blk<1, 8>(row);
            a_lse += lse_blk<8, 24>(row);
            a_lse += lse_blk<24, 31>(row);
            a_lse += lse_blk<31, 45>(row);
            a_lse += lse_blk<45, 51>(row);
            a_lse += lse_blk<51, 53>(row);
            a_lse += lse_blk<53, 55>(row);
            a_lse += lse_blk<58, 99>(row);
        }
        __syncthreads();
    }

    // warp reduce, then 3-warp combine
#pragma unroll
    for (int o = 16; o > 0; o >>= 1) {
        a_mse += __shfl_xor_sync(0xFFFFFFFFu, a_mse, o);
        a_dot += __shfl_xor_sync(0xFFFFFFFFu, a_dot, o);
        a_lse += __shfl_xor_sync(0xFFFFFFFFu, a_lse, o);
    }
    int wid = threadIdx.x >> 5, lid = threadIdx.x & 31;
    if (lid == 0) { wred[0][wid] = a_mse; wred[1][wid] = a_dot; wred[2][wid] = a_lse; }
    __syncthreads();
    if (threadIdx.x == 0) {
        atomicAdd(&g_mse, wred[0][0] + wred[0][1] + wred[0][2]);
        atomicAdd(&g_dot, wred[1][0] + wred[1][1] + wred[1][2]);
        atomicAdd(&g_lse, wred[2][0] + wred[2][1] + wred[2][2]);
    }
}

// ---------------- finalize ----------------
__global__ void k_final(float* __restrict__ out, int B) {
    if (threadIdx.x != 0) return;
    unsigned mcnt = 0, fcnt = 0;
    for (int k = 0; k < 10; k++) { mcnt += g_hist[k]; fcnt += g_hist[100 + k]; }
    float mc = fmaxf((float)mcnt, 1.0f);
    float fc = fmaxf((float)fcnt, 1.0f);
    float kld = 0.f;
    for (int i = 0; i < 100; i++) {
        float p = (float)g_hist[i] / mc;
        float q = (float)g_hist[100 + i] / fc;
        if (p > 0.f && q > 0.f) kld += p * logf(p / q);
    }
    float fB = (float)B;
    float mse = g_mse / fB;
    float ce = (g_lse - g_dot) / fB;
    float akld = 0.5f * kld;
    out[0] = 0.5f * (mse + ce) + akld;   // (1-alpha)*(mse+ce)+alpha*kld, alpha=0.5
    out[1] = mse;
    out[2] = ce;
    out[3] = akld;
}

// ---------------- launcher ----------------
extern "C" void kernel_launch(void* const* d_in, const int* in_sizes, int n_in,
                              void* d_out, int out_size) {
    const float* enc = (const float*)d_in[0];   // [B,12]
    const float* dec = (const float*)d_in[1];   // [B,99]
    const float* tru = (const float*)d_in[2];   // [B,99]
    int B = in_sizes[1] / NCOLS;
    float* out = (float*)d_out;

    k_init<<<1, 256>>>();
    k_minmax<<<296, 256>>>((const float4*)enc, B);
    k_hist<<<296, 256>>>((const float4*)enc, B);

    int nt = (B + TILE_R - 1) / TILE_R;
    int mg = 148 * 6;
    if (mg > nt) mg = nt;
    k_main<<<mg, TPB_MAIN>>>(dec, tru, B);

    k_final<<<1, 32>>>(out, B);
}

// round 2
// speedup vs baseline: 1.3191x; 1.3191x over previous
#include <cuda_runtime.h>

static constexpr int NCOLS = 99;
static constexpr int TPB   = 128;   // threads per block, k_main
static constexpr int TILE  = 128;   // rows per tile (one thread per row in LSE phase)

// ---------------- device scratch (memset-initialized, no allocation) -------
struct Zeros {
    double   acc[3];       // [0]=sum (d-t)^2 cont, [1]=sum d*t ce, [2]=sum lse
    unsigned hist[200];    // [sex(2)][feat(10)][bin(10)]
    unsigned maxkey[10];
    unsigned done[2];      // [0]: k_prep grid sync, [1]: k_main finalize ticket
};
__device__ Zeros gz;
__device__ unsigned g_minkey[10];   // memset 0xFF

// monotonic float<->uint key (order preserving, incl. negatives)
__device__ __forceinline__ unsigned f2key(float f) {
    unsigned u = __float_as_uint(f);
    return (u & 0x80000000u) ? ~u : (u | 0x80000000u);
}
__device__ __forceinline__ float key2f(unsigned k) {
    unsigned u = (k & 0x80000000u) ? (k ^ 0x80000000u) : ~k;
    return __uint_as_float(u);
}

// ---------------- k_prep: minmax -> grid-sync -> histogram -----------------
__global__ void __launch_bounds__(256)
k_prep(const float4* __restrict__ e4, int B) {
    __shared__ float s_mn[8][10], s_mx[8][10];
    __shared__ unsigned sh[200];
    __shared__ float smn[10], swid[10];
    const int t = threadIdx.x, lane = t & 31, w = t >> 5;
    const int stride = gridDim.x * blockDim.x;
    const int gbase  = blockIdx.x * blockDim.x + t;

    // --- phase A: per-column min/max of encoded[:, 0:10] ---
    float mn[10], mx[10];
    const float INF = __int_as_float(0x7f800000);
#pragma unroll
    for (int i = 0; i < 10; i++) { mn[i] = INF; mx[i] = -INF; }
    for (int r = gbase; r < B; r += stride) {
        float4 a = e4[3*r], b = e4[3*r+1], c = e4[3*r+2];
        float v[10] = {a.x,a.y,a.z,a.w,b.x,b.y,b.z,b.w,c.x,c.y};
#pragma unroll
        for (int i = 0; i < 10; i++) {
            mn[i] = fminf(mn[i], v[i]);
            mx[i] = fmaxf(mx[i], v[i]);
        }
    }
#pragma unroll
    for (int i = 0; i < 10; i++) {
#pragma unroll
        for (int o = 16; o > 0; o >>= 1) {
            mn[i] = fminf(mn[i], __shfl_xor_sync(0xFFFFFFFFu, mn[i], o));
            mx[i] = fmaxf(mx[i], __shfl_xor_sync(0xFFFFFFFFu, mx[i], o));
        }
    }
    if (lane == 0) {
#pragma unroll
        for (int i = 0; i < 10; i++) { s_mn[w][i] = mn[i]; s_mx[w][i] = mx[i]; }
    }
    if (t < 200) sh[t] = 0u;
    __syncthreads();
    if (t < 10) {
        float m = s_mn[0][t], x = s_mx[0][t];
#pragma unroll
        for (int ww = 1; ww < 8; ww++) { m = fminf(m, s_mn[ww][t]); x = fmaxf(x, s_mx[ww][t]); }
        atomicMin(&g_minkey[t], f2key(m));
        atomicMax(&gz.maxkey[t], f2key(x));
    }

    // --- grid sync (all CTAs resident: grid=296 <= 148*2 min residency) ---
    __threadfence();
    __syncthreads();
    if (t == 0) {
        atomicAdd(&gz.done[0], 1u);
        while (atomicAdd(&gz.done[0], 0u) < gridDim.x) __nanosleep(64);
    }
    __syncthreads();
    __threadfence();

    // --- phase B: histogram with warp-aggregated shared atomics ---
    if (t < 10) {
        float m = key2f(g_minkey[t]);
        float x = key2f(gz.maxkey[t]);
        smn[t]  = m;
        swid[t] = fmaxf(x - m, 1e-12f);
    }
    __syncthreads();

    const int B_al = B & ~31;   // full-warp region (B%32==0 in practice)
    for (int r = gbase; r < B_al; r += stride) {
        float4 a = e4[3*r], b = e4[3*r+1], c = e4[3*r+2];
        unsigned base = (c.w == 0.0f) ? 0u : 100u;   // col 11 = sex
        float v[10] = {a.x,a.y,a.z,a.w,b.x,b.y,b.z,b.w,c.x,c.y};
#pragma unroll
        for (int i = 0; i < 10; i++) {
            float tt = (v[i] - smn[i]) / swid[i] * 10.0f;   // match jnp op order
            int bi = (int)floorf(tt);
            bi = bi < 0 ? 0 : (bi > 9 ? 9 : bi);
            unsigned key = base + (unsigned)(i * 10 + bi);
            unsigned msk = __match_any_sync(0xFFFFFFFFu, key);
            if ((msk & ((1u << lane) - 1u)) == 0u)          // lowest-lane leader
                atomicAdd(&sh[key], (unsigned)__popc(msk));
        }
    }
    for (int r = B_al + gbase; r < B; r += stride) {        // scalar tail
        float4 a = e4[3*r], b = e4[3*r+1], c = e4[3*r+2];
        unsigned base = (c.w == 0.0f) ? 0u : 100u;
        float v[10] = {a.x,a.y,a.z,a.w,b.x,b.y,b.z,b.w,c.x,c.y};
#pragma unroll
        for (int i = 0; i < 10; i++) {
            float tt = (v[i] - smn[i]) / swid[i] * 10.0f;
            int bi = (int)floorf(tt);
            bi = bi < 0 ? 0 : (bi > 9 ? 9 : bi);
            atomicAdd(&sh[base + (unsigned)(i * 10 + bi)], 1u);
        }
    }
    __syncthreads();
    if (t < 200 && sh[t]) atomicAdd(&gz.hist[t], sh[t]);
}

// ---------------- k_main: MSE + CE, last-CTA finalize ----------------------
template <int S, int E>
__device__ __forceinline__ float lse_blk(const float* row) {
    float s = 0.f;
#pragma unroll
    for (int c = S; c < E; ++c) s += __expf(row[c]);
    return __logf(s);
}

__device__ __forceinline__ void classify_acc(float d, float t, int c,
                                             float& a_mse, float& a_dot) {
    bool cont = (c == 0) || (c >= 55 && c <= 57);
    float df = d - t;
    if (cont) a_mse = fmaf(df, df, a_mse);
    else      a_dot = fmaf(d, t, a_dot);
}

__global__ void __launch_bounds__(TPB)
k_main(const float* __restrict__ dec, const float* __restrict__ tru,
       float* __restrict__ out, int B) {
    extern __shared__ float sm[];                 // TILE*99 floats
    __shared__ float wr[3][TPB / 32];
    __shared__ int   s_last;

    const int r0   = blockIdx.x * TILE;
    const int rows = min(TILE, B - r0);
    const int nflt = rows * NCOLS;
    const int n4   = nflt >> 2;
    const float4* d4 = (const float4*)(dec + (size_t)r0 * NCOLS);
    const float4* t4 = (const float4*)(tru + (size_t)r0 * NCOLS);
    float4* s4 = (float4*)sm;

    float a_mse = 0.f, a_dot = 0.f;

    // --- phase 1: stream both matrices, 8 loads in flight per thread ---
    int i = threadIdx.x;
    for (; i + 3 * TPB < n4; i += 4 * TPB) {
        float4 dd[4], tt[4];
#pragma unroll
        for (int k = 0; k < 4; k++) { dd[k] = d4[i + k*TPB]; tt[k] = t4[i + k*TPB]; }
#pragma unroll
        for (int k = 0; k < 4; k++) {
            s4[i + k*TPB] = dd[k];
            int c = (4 * (i + k*TPB)) % NCOLS;
            float dv[4] = {dd[k].x, dd[k].y, dd[k].z, dd[k].w};
            float tv[4] = {tt[k].x, tt[k].y, tt[k].z, tt[k].w};
#pragma unroll
            for (int j = 0; j < 4; j++) {
                classify_acc(dv[j], tv[j], c, a_mse, a_dot);
                c = (c == NCOLS - 1) ? 0 : c + 1;
            }
        }
    }
    for (; i < n4; i += TPB) {
        float4 d = d4[i], t = t4[i];
        s4[i] = d;
        int c = (4 * i) % NCOLS;
        float dv[4] = {d.x, d.y, d.z, d.w};
        float tv[4] = {t.x, t.y, t.z, t.w};
#pragma unroll
        for (int j = 0; j < 4; j++) {
            classify_acc(dv[j], tv[j], c, a_mse, a_dot);
            c = (c == NCOLS - 1) ? 0 : c + 1;
        }
    }
    for (int e = (n4 << 2) + threadIdx.x; e < nflt; e += TPB) {   // float tail
        float d = dec[(size_t)r0 * NCOLS + e], t = tru[(size_t)r0 * NCOLS + e];
        sm[e] = d;
        classify_acc(d, t, e % NCOLS, a_mse, a_dot);
    }
    __syncthreads();

    // --- phase 2: one thread per row, blockwise LSE from smem ---
    float a_lse = 0.f;
    if (threadIdx.x < rows) {
        const float* row = sm + threadIdx.x * NCOLS;
        a_lse += lse_blk< 1,  8>(row);
        a_lse += lse_blk< 8, 24>(row);
        a_lse += lse_blk<24, 31>(row);
        a_lse += lse_blk<31, 45>(row);
        a_lse += lse_blk<45, 51>(row);
        a_lse += lse_blk<51, 53>(row);
        a_lse += lse_blk<53, 55>(row);
        a_lse += lse_blk<58, 99>(row);
    }

    // --- block reduce -> double global atomics ---
#pragma unroll
    for (int o = 16; o > 0; o >>= 1) {
        a_mse += __shfl_xor_sync(0xFFFFFFFFu, a_mse, o);
        a_dot += __shfl_xor_sync(0xFFFFFFFFu, a_dot, o);
        a_lse += __shfl_xor_sync(0xFFFFFFFFu, a_lse, o);
    }
    int wid = threadIdx.x >> 5, lid = threadIdx.x & 31;
    if (lid == 0) { wr[0][wid] = a_mse; wr[1][wid] = a_dot; wr[2][wid] = a_lse; }
    __syncthreads();
    if (threadIdx.x == 0) {
        float m = 0.f, d = 0.f, l = 0.f;
#pragma unroll
        for (int k = 0; k < TPB / 32; k++) { m += wr[0][k]; d += wr[1][k]; l += wr[2][k]; }
        atomicAdd(&gz.acc[0], (double)m);
        atomicAdd(&gz.acc[1], (double)d);
        atomicAdd(&gz.acc[2], (double)l);
        __threadfence();
        unsigned tk = atomicAdd(&gz.done[1], 1u);
        s_last = (tk == gridDim.x - 1u) ? 1 : 0;
    }
    __syncthreads();

    // --- last CTA finalizes (double precision, 32 lanes) ---
    if (s_last && threadIdx.x < 32) {
        __threadfence();
        int lane32 = threadIdx.x;
        double mcnt = (lane32 < 10) ? (double)gz.hist[lane32]       : 0.0;
        double fcnt = (lane32 < 10) ? (double)gz.hist[100 + lane32] : 0.0;
#pragma unroll
        for (int o = 16; o > 0; o >>= 1) {
            mcnt += __shfl_xor_sync(0xFFFFFFFFu, mcnt, o);
            fcnt += __shfl_xor_sync(0xFFFFFFFFu, fcnt, o);
        }
        double mc = fmax(mcnt, 1.0), fc = fmax(fcnt, 1.0);
        double kld = 0.0;
#pragma unroll
        for (int k = 0; k < 4; k++) {
            int b = k * 32 + lane32;
            if (b < 100) {
                double p = (double)gz.hist[b] / mc;
                double q = (double)gz.hist[100 + b] / fc;
                if (p > 0.0 && q > 0.0) kld += p * log(p / q);
            }
        }
#pragma unroll
        for (int o = 16; o > 0; o >>= 1)
            kld += __shfl_xor_sync(0xFFFFFFFFu, kld, o);
        if (lane32 == 0) {
            double mseS = atomicAdd(&gz.acc[0], 0.0);
            double dotS = atomicAdd(&gz.acc[1], 0.0);
            double lseS = atomicAdd(&gz.acc[2], 0.0);
            double fB   = (double)B;
            double mse  = mseS / fB;
            double ce   = (lseS - dotS) / fB;
            double akld = 0.5 * kld;
            out[0] = (float)(0.5 * (mse + ce) + akld);
            out[1] = (float)mse;
            out[2] = (float)ce;
            out[3] = (float)akld;
        }
    }
}

// ---------------- launcher ----------------
extern "C" void kernel_launch(void* const* d_in, const int* in_sizes, int n_in,
                              void* d_out, int out_size) {
    const float* enc = (const float*)d_in[0];   // [B,12]
    const float* dec = (const float*)d_in[1];   // [B,99]
    const float* tru = (const float*)d_in[2];   // [B,99]
    const int B = in_sizes[1] / NCOLS;
    float* out = (float*)d_out;

    void *pz = nullptr, *pk = nullptr;
    cudaGetSymbolAddress(&pz, gz);
    cudaGetSymbolAddress(&pk, g_minkey);
    cudaMemsetAsync(pz, 0, sizeof(Zeros), 0);
    cudaMemsetAsync(pk, 0xFF, 10 * sizeof(unsigned), 0);

    k_prep<<<296, 256>>>((const float4*)enc, B);

    const int smem = TILE * NCOLS * (int)sizeof(float);   // 50688 B
    cudaFuncSetAttribute(k_main, cudaFuncAttributeMaxDynamicSharedMemorySize, smem);
    const int grid = (B + TILE - 1) / TILE;
    k_main<<<grid, TPB, smem>>>(dec, tru, out, B);
}